// round 14
// baseline (speedup 1.0000x reference)
#include <cuda_runtime.h>
#include <cuda_fp16.h>
#include <cstdint>
#include <math.h>

#define NMAX 100000
#define C    64
#define HID  16
#define KNN  16
#define FULL 0xFFFFFFFFu

// Scratch (device globals)
__device__ float g_rowstat[(size_t)NMAX * 2];
__device__ float g_z[(size_t)NMAX * 2];
__device__ __align__(16) __half2 g_xh2[(size_t)NMAX * C / 2];  // fp16 mirror of x_F
__device__ __align__(16) __half2 g_outh[(size_t)NMAX * C / 2]; // fp16 outse

// ---------------------------------------------------------------------------
// Kernel 0: fp16 mirror of x_F (row = 128B = one cache line).
// ---------------------------------------------------------------------------
__global__ __launch_bounds__(256) void k0_tohalf(const float* __restrict__ xF, int n8)
{
    int i = blockIdx.x * blockDim.x + threadIdx.x;
    if (i >= n8) return;
    const float4* src = (const float4*)xF;
    float4 a = __ldg(src + 2 * i);
    float4 b = __ldg(src + 2 * i + 1);
    __half2 h0 = __floats2half2_rn(a.x, a.y);
    __half2 h1 = __floats2half2_rn(a.z, a.w);
    __half2 h2 = __floats2half2_rn(b.x, b.y);
    __half2 h3 = __floats2half2_rn(b.z, b.w);
    ((uint4*)g_xh2)[i] = make_uint4(*(unsigned*)&h0, *(unsigned*)&h1,
                                    *(unsigned*)&h2, *(unsigned*)&h3);
}

// ---------------------------------------------------------------------------
// Kernel 1: channel attention, QUARTER-WARP per point (4 points/warp).
//   Direct LDG.128 gather (fp16 row = 1 line), half2 pooling, two low-
//   register butterfly passes. __launch_bounds__(256,5) forces 5 blocks/SM
//   (40 warps) — all ancillary loads de-hoisted below the gather to shrink
//   live ranges.
// ---------------------------------------------------------------------------
__global__ __launch_bounds__(256, 5) void k1_gate(
    const float* __restrict__ xF,
    const float* __restrict__ W1,   // (C, HID)
    const float* __restrict__ b1,   // (HID,)
    const float* __restrict__ W2,   // (HID, C)
    const float* __restrict__ b2,   // (C,)
    const int*   __restrict__ idx,  // (N, KNN)
    int N)
{
    __shared__ float4 sW1a[HID * 8], sW1b[HID * 8];
    __shared__ float4 sW2a[HID * 8], sW2b[HID * 8];

    const int tid = threadIdx.x;
    for (int i = tid; i < HID * 8; i += blockDim.x) {
        int j = i >> 3, h = i & 7;
        sW1a[i] = make_float4(W1[(8*h+0)*HID + j], W1[(8*h+1)*HID + j],
                              W1[(8*h+2)*HID + j], W1[(8*h+3)*HID + j]);
        sW1b[i] = make_float4(W1[(8*h+4)*HID + j], W1[(8*h+5)*HID + j],
                              W1[(8*h+6)*HID + j], W1[(8*h+7)*HID + j]);
        sW2a[i] = __ldg((const float4*)W2 + j * 16 + 2 * h);
        sW2b[i] = __ldg((const float4*)W2 + j * 16 + 2 * h + 1);
    }
    __syncthreads();

    const int lane  = tid & 31;
    const int q     = lane >> 3;
    const int ql    = lane & 7;
    const int qbase = lane & 24;
    const int warp  = blockIdx.x * (blockDim.x >> 5) + (tid >> 5);
    if (4 * warp >= N) return;
    int n = 4 * warp + q;
    if (n >= N) n = N - 1;

    // ---- neighbor indices ----
    const int4* ib = (const int4*)(idx + (size_t)n * KNN);
    int4 i0 = __ldg(ib + 0), i1 = __ldg(ib + 1),
         i2 = __ldg(ib + 2), i3 = __ldg(ib + 3);
    const int nb[KNN] = { i0.x, i0.y, i0.z, i0.w,  i1.x, i1.y, i1.z, i1.w,
                          i2.x, i2.y, i2.z, i2.w,  i3.x, i3.y, i3.z, i3.w };

    // ---- gather + pool: native half2 (4 HMAX2 + 4 HADD2 per k) ----
    const __half NEGINF = __ushort_as_half((unsigned short)0xFC00);
    __half2 mh0 = __half2half2(NEGINF), mh1 = __half2half2(NEGINF);
    __half2 mh2 = __half2half2(NEGINF), mh3 = __half2half2(NEGINF);
    __half2 sh0 = __float2half2_rn(0.f), sh1 = __float2half2_rn(0.f);
    __half2 sh2 = __float2half2_rn(0.f), sh3 = __float2half2_rn(0.f);
    #pragma unroll
    for (int k = 0; k < KNN; k++) {
        uint4 raw = __ldg((const uint4*)(g_xh2 + (size_t)nb[k] * (C/2)) + ql);
        __half2 r0 = *(__half2*)&raw.x, r1 = *(__half2*)&raw.y;
        __half2 r2 = *(__half2*)&raw.z, r3 = *(__half2*)&raw.w;
        mh0 = __hmax2(mh0, r0); mh1 = __hmax2(mh1, r1);
        mh2 = __hmax2(mh2, r2); mh3 = __hmax2(mh3, r3);
        sh0 = __hadd2(sh0, r0); sh1 = __hadd2(sh1, r1);
        sh2 = __hadd2(sh2, r2); sh3 = __hadd2(sh3, r3);
    }

    // ================= PASS A: mean path =================
    float pm[HID];
    {
        const float inv = 1.f / KNN;
        float2 s0 = __half22float2(sh0), s1 = __half22float2(sh1),
               s2 = __half22float2(sh2), s3 = __half22float2(sh3);
        float m0=s0.x*inv, m1=s0.y*inv, m2=s1.x*inv, m3=s1.y*inv;
        float m4=s2.x*inv, m5=s2.y*inv, m6=s3.x*inv, m7=s3.y*inv;
        #pragma unroll
        for (int j = 0; j < HID; j++) {
            float4 wa = sW1a[j * 8 + ql], wb = sW1b[j * 8 + ql];
            pm[j] = m0*wa.x + m1*wa.y + m2*wa.z + m3*wa.w
                  + m4*wb.x + m5*wb.y + m6*wb.z + m7*wb.w;
        }
    }
    #pragma unroll
    for (int step = 0; step < 3; step++) {
        const int  off = 4 >> step;   // 4,2,1 (within quarter)
        const int  nv  = 8 >> step;   // 8,4,2
        const bool up  = (ql & off) != 0;
        #pragma unroll
        for (int i = 0; i < nv; i++) {
            float send = up ? pm[i] : pm[i + nv];
            float recv = __shfl_xor_sync(FULL, send, off);
            float keep = up ? pm[i + nv] : pm[i];
            pm[i] = keep + recv;
        }
    }
    const float mean0 = pm[0], mean1 = pm[1];

    // ================= PASS B: max path =================
    float px[HID];
    {
        float2 c0 = __half22float2(mh0), c1 = __half22float2(mh1),
               c2 = __half22float2(mh2), c3 = __half22float2(mh3);
        #pragma unroll
        for (int j = 0; j < HID; j++) {
            float4 wa = sW1a[j * 8 + ql], wb = sW1b[j * 8 + ql];
            px[j] = c0.x*wa.x + c0.y*wa.y + c1.x*wa.z + c1.y*wa.w
                  + c2.x*wb.x + c2.y*wb.y + c3.x*wb.z + c3.y*wb.w;
        }
    }
    #pragma unroll
    for (int step = 0; step < 3; step++) {
        const int  off = 4 >> step;
        const int  nv  = 8 >> step;
        const bool up  = (ql & off) != 0;
        #pragma unroll
        for (int i = 0; i < nv; i++) {
            float send = up ? px[i] : px[i + nv];
            float recv = __shfl_xor_sync(FULL, send, off);
            float keep = up ? px[i + nv] : px[i];
            px[i] = keep + recv;
        }
    }

    // biases loaded late (short live range)
    const float2 b1v = __ldg((const float2*)b1 + ql);
    float hs0 = fmaxf(mean0 + b1v.x, 0.f) + fmaxf(px[0] + b1v.x, 0.f);
    float hs1 = fmaxf(mean1 + b1v.y, 0.f) + fmaxf(px[1] + b1v.y, 0.f);

    // ---- layer 2 (fp32) ----
    const float4 b2a = __ldg((const float4*)b2 + 2 * ql);
    const float4 b2b = __ldg((const float4*)b2 + 2 * ql + 1);
    float4 a0 = make_float4(2.f*b2a.x, 2.f*b2a.y, 2.f*b2a.z, 2.f*b2a.w);
    float4 a1 = make_float4(2.f*b2b.x, 2.f*b2b.y, 2.f*b2b.z, 2.f*b2b.w);
    #pragma unroll
    for (int jj = 0; jj < 8; jj++) {
        float h0 = __shfl_sync(FULL, hs0, qbase | jj);   // hidden 2jj
        float h1 = __shfl_sync(FULL, hs1, qbase | jj);   // hidden 2jj+1
        float4 wa = sW2a[(2*jj) * 8 + ql],   wb = sW2b[(2*jj) * 8 + ql];
        a0.x += h0*wa.x; a0.y += h0*wa.y; a0.z += h0*wa.z; a0.w += h0*wa.w;
        a1.x += h0*wb.x; a1.y += h0*wb.y; a1.z += h0*wb.z; a1.w += h0*wb.w;
        float4 wc = sW2a[(2*jj+1) * 8 + ql], wd = sW2b[(2*jj+1) * 8 + ql];
        a0.x += h1*wc.x; a0.y += h1*wc.y; a0.z += h1*wc.z; a0.w += h1*wc.w;
        a1.x += h1*wd.x; a1.y += h1*wd.y; a1.z += h1*wd.z; a1.w += h1*wd.w;
    }

    // fp32 x row loaded late (short live range)
    float4 xv0 = __ldg((const float4*)(xF + (size_t)n * C) + 2 * ql);
    float4 xv1 = __ldg((const float4*)(xF + (size_t)n * C) + 2 * ql + 1);
    float4 o0, o1;
    o0.x = xv0.x / (1.f + __expf(-a0.x));
    o0.y = xv0.y / (1.f + __expf(-a0.y));
    o0.z = xv0.z / (1.f + __expf(-a0.z));
    o0.w = xv0.w / (1.f + __expf(-a0.w));
    o1.x = xv1.x / (1.f + __expf(-a1.x));
    o1.y = xv1.y / (1.f + __expf(-a1.y));
    o1.z = xv1.z / (1.f + __expf(-a1.z));
    o1.w = xv1.w / (1.f + __expf(-a1.w));

    // ---- write outse in fp16 (one uint4 per lane) ----
    {
        __half2 w0 = __floats2half2_rn(o0.x, o0.y);
        __half2 w1 = __floats2half2_rn(o0.z, o0.w);
        __half2 w2 = __floats2half2_rn(o1.x, o1.y);
        __half2 w3 = __floats2half2_rn(o1.z, o1.w);
        ((uint4*)(g_outh + (size_t)n * (C/2)))[ql] =
            make_uint4(*(unsigned*)&w0, *(unsigned*)&w1,
                       *(unsigned*)&w2, *(unsigned*)&w3);
    }

    // ---- rowsum/rowmax over the quarter (from fp32 values) ----
    float s  = (o0.x + o0.y + o0.z + o0.w) + (o1.x + o1.y + o1.z + o1.w);
    float mm = fmaxf(fmaxf(fmaxf(o0.x, o0.y), fmaxf(o0.z, o0.w)),
                     fmaxf(fmaxf(o1.x, o1.y), fmaxf(o1.z, o1.w)));
    #pragma unroll
    for (int off = 4; off >= 1; off >>= 1) {
        s  += __shfl_xor_sync(FULL, s, off);
        mm  = fmaxf(mm, __shfl_xor_sync(FULL, mm, off));
    }
    if (ql == 0)
        *(float2*)(g_rowstat + 2 * (size_t)n) = make_float2(s, mm);
}

// ---------------------------------------------------------------------------
// Kernel 2: z = (mean, max) pooled over neighbors, via per-point rowstats.
// ---------------------------------------------------------------------------
__global__ __launch_bounds__(256) void k2_z(const int* __restrict__ idx, int N)
{
    int n = blockIdx.x * blockDim.x + threadIdx.x;
    if (n >= N) return;
    const int4* ib = (const int4*)(idx + (size_t)n * KNN);
    int4 q0 = __ldg(ib + 0), q1 = __ldg(ib + 1),
         q2 = __ldg(ib + 2), q3 = __ldg(ib + 3);
    const int nb[KNN] = { q0.x, q0.y, q0.z, q0.w,  q1.x, q1.y, q1.z, q1.w,
                          q2.x, q2.y, q2.z, q2.w,  q3.x, q3.y, q3.z, q3.w };
    float s = 0.f, mx = -INFINITY;
    #pragma unroll
    for (int k = 0; k < KNN; k++) {
        float2 rs = __ldg((const float2*)(g_rowstat + 2 * (size_t)nb[k]));
        s += rs.x;
        mx = fmaxf(mx, rs.y);
    }
    *(float2*)(g_z + 2 * (size_t)n) = make_float2(s * (1.f / (KNN * C)), mx);
}

// ---------------------------------------------------------------------------
// Kernel 3 (fused gate + multiply): QUARTER-WARP per point.
//   outse read as fp16 (one uint4 per lane), hoisted before the tap chain.
// ---------------------------------------------------------------------------
__global__ __launch_bounds__(256) void k3_fused(
    const float* __restrict__ conv_w,   // (27, 2)
    const int*   __restrict__ conv_idx, // (N, 27)
    float*       __restrict__ out,
    int N)
{
    __shared__ float2 scw[28];
    if (threadIdx.x < 27)
        scw[threadIdx.x] = __ldg((const float2*)conv_w + threadIdx.x);
    if (threadIdx.x == 27)
        scw[27] = make_float2(0.f, 0.f);
    __syncthreads();

    const int lane = threadIdx.x & 31;
    const int q    = lane >> 3;
    const int ql   = lane & 7;
    const int warp = blockIdx.x * (blockDim.x >> 5) + (threadIdx.x >> 5);
    if (4 * warp >= N) return;
    int n = 4 * warp + q;
    if (n >= N) n = N - 1;

    // independent streaming load first (overlap with conv gather latency)
    uint4 oh = __ldg((const uint4*)(g_outh + (size_t)n * (C/2)) + ql);

    const int* cb = conv_idx + (size_t)n * 27;
    int mi[4];
    #pragma unroll
    for (int i = 0; i < 4; i++) {
        int k = 4 * ql + i;
        mi[i] = (k < 27) ? __ldg(cb + k) : -1;
    }
    float f = 0.f;
    #pragma unroll
    for (int i = 0; i < 4; i++) {
        int k  = 4 * ql + i;
        int mc = mi[i] < 0 ? 0 : mi[i];
        float2 zz = __ldg((const float2*)g_z + mc);      // unconditional
        float2 cw = scw[k < 27 ? k : 27];
        float  contrib = zz.x * cw.x + zz.y * cw.y;
        f += (mi[i] >= 0) ? contrib : 0.f;
    }
    #pragma unroll
    for (int off = 4; off >= 1; off >>= 1)
        f += __shfl_xor_sync(FULL, f, off);

    float sg = 1.f / (1.f + __expf(-f));
    float2 f0 = __half22float2(*(__half2*)&oh.x);
    float2 f1 = __half22float2(*(__half2*)&oh.y);
    float2 f2 = __half22float2(*(__half2*)&oh.z);
    float2 f3 = __half22float2(*(__half2*)&oh.w);
    ((float4*)(out + (size_t)n * C))[2 * ql] =
        make_float4(f0.x * sg, f0.y * sg, f1.x * sg, f1.y * sg);
    ((float4*)(out + (size_t)n * C))[2 * ql + 1] =
        make_float4(f2.x * sg, f2.y * sg, f3.x * sg, f3.y * sg);
}

// ---------------------------------------------------------------------------
// Launch
// ---------------------------------------------------------------------------
extern "C" void kernel_launch(void* const* d_in, const int* in_sizes, int n_in,
                              void* d_out, int out_size)
{
    const float* xF  = (const float*)d_in[0];
    const float* W1  = (const float*)d_in[1];
    const float* b1  = (const float*)d_in[2];
    const float* W2  = (const float*)d_in[3];
    const float* b2  = (const float*)d_in[4];
    const float* cw  = (const float*)d_in[5];
    const int*   idx = (const int*)d_in[6];
    const int*   cid = (const int*)d_in[7];
    float*       out = (float*)d_out;

    const int N  = in_sizes[0] / C;                // 100000
    const int n8 = (N * C) / 8;
    const int nquads    = (N + 3) / 4;             // 4 points per warp
    const int qw_blocks = (nquads + 7) / 8;        // 8 warps per block

    k0_tohalf<<<(n8 + 255) / 256, 256>>>(xF, n8);
    k1_gate  <<<qw_blocks, 256>>>(xF, W1, b1, W2, b2, idx, N);
    k2_z     <<<(N + 255) / 256, 256>>>(idx, N);
    k3_fused <<<qw_blocks, 256>>>(cw, cid, out, N);
}

// round 15
// speedup vs baseline: 1.1482x; 1.1482x over previous
#include <cuda_runtime.h>
#include <cuda_fp16.h>
#include <cstdint>
#include <math.h>

#define NMAX 100000
#define C    64
#define HID  16
#define KNN  16
#define FULL 0xFFFFFFFFu

// Scratch (device globals)
__device__ float g_rowstat[(size_t)NMAX * 2];
__device__ float g_z[(size_t)NMAX * 2];
__device__ __align__(16) __half2 g_xh2[(size_t)NMAX * C / 2];  // fp16 mirror of x_F
__device__ __align__(16) __half2 g_outh[(size_t)NMAX * C / 2]; // fp16 outse

// ---------------------------------------------------------------------------
// Kernel 0: fp16 mirror of x_F (row = 128B = one cache line).
// ---------------------------------------------------------------------------
__global__ __launch_bounds__(256) void k0_tohalf(const float* __restrict__ xF, int n8)
{
    int i = blockIdx.x * blockDim.x + threadIdx.x;
    if (i >= n8) return;
    const float4* src = (const float4*)xF;
    float4 a = __ldg(src + 2 * i);
    float4 b = __ldg(src + 2 * i + 1);
    __half2 h0 = __floats2half2_rn(a.x, a.y);
    __half2 h1 = __floats2half2_rn(a.z, a.w);
    __half2 h2 = __floats2half2_rn(b.x, b.y);
    __half2 h3 = __floats2half2_rn(b.z, b.w);
    ((uint4*)g_xh2)[i] = make_uint4(*(unsigned*)&h0, *(unsigned*)&h1,
                                    *(unsigned*)&h2, *(unsigned*)&h3);
}

// ---------------------------------------------------------------------------
// Kernel 1: channel attention, QUARTER-WARP per point (4 points/warp).
//   R13 best core: direct gather (fp16 row = 1 line) via __ldcg (L2-only,
//   no L1 allocate — gathered rows have ~no within-SM reuse), half2 pooling,
//   two 8-lane butterfly passes. Output written as fp16 (g_outh).
// ---------------------------------------------------------------------------
__global__ __launch_bounds__(256) void k1_gate(
    const float* __restrict__ xF,
    const float* __restrict__ W1,   // (C, HID)
    const float* __restrict__ b1,   // (HID,)
    const float* __restrict__ W2,   // (HID, C)
    const float* __restrict__ b2,   // (C,)
    const int*   __restrict__ idx,  // (N, KNN)
    int N)
{
    __shared__ float4 sW1a[HID * 8], sW1b[HID * 8];
    __shared__ float4 sW2a[HID * 8], sW2b[HID * 8];

    const int tid = threadIdx.x;
    for (int i = tid; i < HID * 8; i += blockDim.x) {
        int j = i >> 3, h = i & 7;
        sW1a[i] = make_float4(W1[(8*h+0)*HID + j], W1[(8*h+1)*HID + j],
                              W1[(8*h+2)*HID + j], W1[(8*h+3)*HID + j]);
        sW1b[i] = make_float4(W1[(8*h+4)*HID + j], W1[(8*h+5)*HID + j],
                              W1[(8*h+6)*HID + j], W1[(8*h+7)*HID + j]);
        sW2a[i] = __ldg((const float4*)W2 + j * 16 + 2 * h);
        sW2b[i] = __ldg((const float4*)W2 + j * 16 + 2 * h + 1);
    }
    __syncthreads();

    const int lane  = tid & 31;
    const int q     = lane >> 3;
    const int ql    = lane & 7;
    const int qbase = lane & 24;
    const int warp  = blockIdx.x * (blockDim.x >> 5) + (tid >> 5);
    if (4 * warp >= N) return;
    int n = 4 * warp + q;
    if (n >= N) n = N - 1;

    const float2 b1v = __ldg((const float2*)b1 + ql);

    // independent of the gather: issue early to overlap
    float4 xv0 = __ldg((const float4*)(xF + (size_t)n * C) + 2 * ql);
    float4 xv1 = __ldg((const float4*)(xF + (size_t)n * C) + 2 * ql + 1);

    // ---- neighbor indices ----
    const int4* ib = (const int4*)(idx + (size_t)n * KNN);
    int4 i0 = __ldg(ib + 0), i1 = __ldg(ib + 1),
         i2 = __ldg(ib + 2), i3 = __ldg(ib + 3);
    const int nb[KNN] = { i0.x, i0.y, i0.z, i0.w,  i1.x, i1.y, i1.z, i1.w,
                          i2.x, i2.y, i2.z, i2.w,  i3.x, i3.y, i3.z, i3.w };

    // ---- gather + pool: native half2 (4 HMAX2 + 4 HADD2 per k).
    //      __ldcg: L2-only, avoid L1 allocation for no-reuse rows. ----
    const __half NEGINF = __ushort_as_half((unsigned short)0xFC00);
    __half2 mh0 = __half2half2(NEGINF), mh1 = __half2half2(NEGINF);
    __half2 mh2 = __half2half2(NEGINF), mh3 = __half2half2(NEGINF);
    __half2 sh0 = __float2half2_rn(0.f), sh1 = __float2half2_rn(0.f);
    __half2 sh2 = __float2half2_rn(0.f), sh3 = __float2half2_rn(0.f);
    #pragma unroll
    for (int k = 0; k < KNN; k++) {
        uint4 raw = __ldcg((const uint4*)(g_xh2 + (size_t)nb[k] * (C/2)) + ql);
        __half2 r0 = *(__half2*)&raw.x, r1 = *(__half2*)&raw.y;
        __half2 r2 = *(__half2*)&raw.z, r3 = *(__half2*)&raw.w;
        mh0 = __hmax2(mh0, r0); mh1 = __hmax2(mh1, r1);
        mh2 = __hmax2(mh2, r2); mh3 = __hmax2(mh3, r3);
        sh0 = __hadd2(sh0, r0); sh1 = __hadd2(sh1, r1);
        sh2 = __hadd2(sh2, r2); sh3 = __hadd2(sh3, r3);
    }

    // ================= PASS A: mean path =================
    float pm[HID];
    {
        const float inv = 1.f / KNN;
        float2 s0 = __half22float2(sh0), s1 = __half22float2(sh1),
               s2 = __half22float2(sh2), s3 = __half22float2(sh3);
        float m0=s0.x*inv, m1=s0.y*inv, m2=s1.x*inv, m3=s1.y*inv;
        float m4=s2.x*inv, m5=s2.y*inv, m6=s3.x*inv, m7=s3.y*inv;
        #pragma unroll
        for (int j = 0; j < HID; j++) {
            float4 wa = sW1a[j * 8 + ql], wb = sW1b[j * 8 + ql];
            pm[j] = m0*wa.x + m1*wa.y + m2*wa.z + m3*wa.w
                  + m4*wb.x + m5*wb.y + m6*wb.z + m7*wb.w;
        }
    }
    #pragma unroll
    for (int step = 0; step < 3; step++) {
        const int  off = 4 >> step;   // 4,2,1 (within quarter)
        const int  nv  = 8 >> step;   // 8,4,2
        const bool up  = (ql & off) != 0;
        #pragma unroll
        for (int i = 0; i < nv; i++) {
            float send = up ? pm[i] : pm[i + nv];
            float recv = __shfl_xor_sync(FULL, send, off);
            float keep = up ? pm[i + nv] : pm[i];
            pm[i] = keep + recv;
        }
    }
    const float mean0 = pm[0], mean1 = pm[1];

    // ================= PASS B: max path =================
    float px[HID];
    {
        float2 c0 = __half22float2(mh0), c1 = __half22float2(mh1),
               c2 = __half22float2(mh2), c3 = __half22float2(mh3);
        #pragma unroll
        for (int j = 0; j < HID; j++) {
            float4 wa = sW1a[j * 8 + ql], wb = sW1b[j * 8 + ql];
            px[j] = c0.x*wa.x + c0.y*wa.y + c1.x*wa.z + c1.y*wa.w
                  + c2.x*wb.x + c2.y*wb.y + c3.x*wb.z + c3.y*wb.w;
        }
    }
    #pragma unroll
    for (int step = 0; step < 3; step++) {
        const int  off = 4 >> step;
        const int  nv  = 8 >> step;
        const bool up  = (ql & off) != 0;
        #pragma unroll
        for (int i = 0; i < nv; i++) {
            float send = up ? px[i] : px[i + nv];
            float recv = __shfl_xor_sync(FULL, send, off);
            float keep = up ? px[i + nv] : px[i];
            px[i] = keep + recv;
        }
    }

    float hs0 = fmaxf(mean0 + b1v.x, 0.f) + fmaxf(px[0] + b1v.x, 0.f);
    float hs1 = fmaxf(mean1 + b1v.y, 0.f) + fmaxf(px[1] + b1v.y, 0.f);

    // ---- layer 2 (fp32) ----
    const float4 b2a = __ldg((const float4*)b2 + 2 * ql);
    const float4 b2b = __ldg((const float4*)b2 + 2 * ql + 1);
    float4 a0 = make_float4(2.f*b2a.x, 2.f*b2a.y, 2.f*b2a.z, 2.f*b2a.w);
    float4 a1 = make_float4(2.f*b2b.x, 2.f*b2b.y, 2.f*b2b.z, 2.f*b2b.w);
    #pragma unroll
    for (int jj = 0; jj < 8; jj++) {
        float h0 = __shfl_sync(FULL, hs0, qbase | jj);   // hidden 2jj
        float h1 = __shfl_sync(FULL, hs1, qbase | jj);   // hidden 2jj+1
        float4 wa = sW2a[(2*jj) * 8 + ql],   wb = sW2b[(2*jj) * 8 + ql];
        a0.x += h0*wa.x; a0.y += h0*wa.y; a0.z += h0*wa.z; a0.w += h0*wa.w;
        a1.x += h0*wb.x; a1.y += h0*wb.y; a1.z += h0*wb.z; a1.w += h0*wb.w;
        float4 wc = sW2a[(2*jj+1) * 8 + ql], wd = sW2b[(2*jj+1) * 8 + ql];
        a0.x += h1*wc.x; a0.y += h1*wc.y; a0.z += h1*wc.z; a0.w += h1*wc.w;
        a1.x += h1*wd.x; a1.y += h1*wd.y; a1.z += h1*wd.z; a1.w += h1*wd.w;
    }

    float4 o0, o1;
    o0.x = xv0.x / (1.f + __expf(-a0.x));
    o0.y = xv0.y / (1.f + __expf(-a0.y));
    o0.z = xv0.z / (1.f + __expf(-a0.z));
    o0.w = xv0.w / (1.f + __expf(-a0.w));
    o1.x = xv1.x / (1.f + __expf(-a1.x));
    o1.y = xv1.y / (1.f + __expf(-a1.y));
    o1.z = xv1.z / (1.f + __expf(-a1.z));
    o1.w = xv1.w / (1.f + __expf(-a1.w));

    // ---- write outse in fp16 (one uint4 per lane) ----
    {
        __half2 w0 = __floats2half2_rn(o0.x, o0.y);
        __half2 w1 = __floats2half2_rn(o0.z, o0.w);
        __half2 w2 = __floats2half2_rn(o1.x, o1.y);
        __half2 w3 = __floats2half2_rn(o1.z, o1.w);
        ((uint4*)(g_outh + (size_t)n * (C/2)))[ql] =
            make_uint4(*(unsigned*)&w0, *(unsigned*)&w1,
                       *(unsigned*)&w2, *(unsigned*)&w3);
    }

    // ---- rowsum/rowmax over the quarter (from fp32 values) ----
    float s  = (o0.x + o0.y + o0.z + o0.w) + (o1.x + o1.y + o1.z + o1.w);
    float mm = fmaxf(fmaxf(fmaxf(o0.x, o0.y), fmaxf(o0.z, o0.w)),
                     fmaxf(fmaxf(o1.x, o1.y), fmaxf(o1.z, o1.w)));
    #pragma unroll
    for (int off = 4; off >= 1; off >>= 1) {
        s  += __shfl_xor_sync(FULL, s, off);
        mm  = fmaxf(mm, __shfl_xor_sync(FULL, mm, off));
    }
    if (ql == 0)
        *(float2*)(g_rowstat + 2 * (size_t)n) = make_float2(s, mm);
}

// ---------------------------------------------------------------------------
// Kernel 2: z = (mean, max) pooled over neighbors, via per-point rowstats.
// ---------------------------------------------------------------------------
__global__ __launch_bounds__(256) void k2_z(const int* __restrict__ idx, int N)
{
    int n = blockIdx.x * blockDim.x + threadIdx.x;
    if (n >= N) return;
    const int4* ib = (const int4*)(idx + (size_t)n * KNN);
    int4 q0 = __ldg(ib + 0), q1 = __ldg(ib + 1),
         q2 = __ldg(ib + 2), q3 = __ldg(ib + 3);
    const int nb[KNN] = { q0.x, q0.y, q0.z, q0.w,  q1.x, q1.y, q1.z, q1.w,
                          q2.x, q2.y, q2.z, q2.w,  q3.x, q3.y, q3.z, q3.w };
    float s = 0.f, mx = -INFINITY;
    #pragma unroll
    for (int k = 0; k < KNN; k++) {
        float2 rs = __ldg((const float2*)(g_rowstat + 2 * (size_t)nb[k]));
        s += rs.x;
        mx = fmaxf(mx, rs.y);
    }
    *(float2*)(g_z + 2 * (size_t)n) = make_float2(s * (1.f / (KNN * C)), mx);
}

// ---------------------------------------------------------------------------
// Kernel 3 (fused gate + multiply): QUARTER-WARP per point.
//   outse read as fp16 (one uint4 per lane), hoisted before the tap chain.
// ---------------------------------------------------------------------------
__global__ __launch_bounds__(256) void k3_fused(
    const float* __restrict__ conv_w,   // (27, 2)
    const int*   __restrict__ conv_idx, // (N, 27)
    float*       __restrict__ out,
    int N)
{
    __shared__ float2 scw[28];
    if (threadIdx.x < 27)
        scw[threadIdx.x] = __ldg((const float2*)conv_w + threadIdx.x);
    if (threadIdx.x == 27)
        scw[27] = make_float2(0.f, 0.f);
    __syncthreads();

    const int lane = threadIdx.x & 31;
    const int q    = lane >> 3;
    const int ql   = lane & 7;
    const int warp = blockIdx.x * (blockDim.x >> 5) + (threadIdx.x >> 5);
    if (4 * warp >= N) return;
    int n = 4 * warp + q;
    if (n >= N) n = N - 1;

    // independent streaming load first (overlap with conv gather latency)
    uint4 oh = __ldcg((const uint4*)(g_outh + (size_t)n * (C/2)) + ql);

    const int* cb = conv_idx + (size_t)n * 27;
    int mi[4];
    #pragma unroll
    for (int i = 0; i < 4; i++) {
        int k = 4 * ql + i;
        mi[i] = (k < 27) ? __ldg(cb + k) : -1;
    }
    float f = 0.f;
    #pragma unroll
    for (int i = 0; i < 4; i++) {
        int k  = 4 * ql + i;
        int mc = mi[i] < 0 ? 0 : mi[i];
        float2 zz = __ldg((const float2*)g_z + mc);      // unconditional
        float2 cw = scw[k < 27 ? k : 27];
        float  contrib = zz.x * cw.x + zz.y * cw.y;
        f += (mi[i] >= 0) ? contrib : 0.f;
    }
    #pragma unroll
    for (int off = 4; off >= 1; off >>= 1)
        f += __shfl_xor_sync(FULL, f, off);

    float sg = 1.f / (1.f + __expf(-f));
    float2 f0 = __half22float2(*(__half2*)&oh.x);
    float2 f1 = __half22float2(*(__half2*)&oh.y);
    float2 f2 = __half22float2(*(__half2*)&oh.z);
    float2 f3 = __half22float2(*(__half2*)&oh.w);
    ((float4*)(out + (size_t)n * C))[2 * ql] =
        make_float4(f0.x * sg, f0.y * sg, f1.x * sg, f1.y * sg);
    ((float4*)(out + (size_t)n * C))[2 * ql + 1] =
        make_float4(f2.x * sg, f2.y * sg, f3.x * sg, f3.y * sg);
}

// ---------------------------------------------------------------------------
// Launch
// ---------------------------------------------------------------------------
extern "C" void kernel_launch(void* const* d_in, const int* in_sizes, int n_in,
                              void* d_out, int out_size)
{
    const float* xF  = (const float*)d_in[0];
    const float* W1  = (const float*)d_in[1];
    const float* b1  = (const float*)d_in[2];
    const float* W2  = (const float*)d_in[3];
    const float* b2  = (const float*)d_in[4];
    const float* cw  = (const float*)d_in[5];
    const int*   idx = (const int*)d_in[6];
    const int*   cid = (const int*)d_in[7];
    float*       out = (float*)d_out;

    const int N  = in_sizes[0] / C;                // 100000
    const int n8 = (N * C) / 8;
    const int nquads    = (N + 3) / 4;             // 4 points per warp
    const int qw_blocks = (nquads + 7) / 8;        // 8 warps per block

    k0_tohalf<<<(n8 + 255) / 256, 256>>>(xF, n8);
    k1_gate  <<<qw_blocks, 256>>>(xF, W1, b1, W2, b2, idx, N);
    k2_z     <<<(N + 255) / 256, 256>>>(idx, N);
    k3_fused <<<qw_blocks, 256>>>(cw, cid, out, N);
}